// round 1
// baseline (speedup 1.0000x reference)
#include <cuda_runtime.h>
#include <stdint.h>
#include <math.h>

// Problem constants (B=8, N=1025, D=64)
#define Bsz    8
#define Nn     1025
#define Dd     64
#define Tt     8192      // B*(N-1)
#define MASKN  8200      // B*N

// GEMM tiling
#define BM     64
#define BN     128
#define SPLITS 8
#define ROWTILES (Tt/BM) // 128

#define SCALE_Q 28.85390081777927f   // log2(e)/0.05
#define C0x    (-28.85390081777927f) // -20*log2(e)
#define LN2f    0.6931471805599453f

// Device scratch (zero-initialized at module load; rows >= count stay 0 forever)
__device__ int   g_pos[Tt];
__device__ int   g_count;
__device__ float g_qn[Tt * Dd];
__device__ float g_kn[Tt * Dd];
__device__ float g_S[SPLITS][Tt];
__device__ float g_bpart[256];

// 2^x for x in [-60, 1]: round-to-nearest split + deg-5 poly, FMA-pipe only.
__device__ __forceinline__ float exp2_poly(float x) {
    float t = x + 12582912.0f;            // 0x4B400000 : round x to int in low bits
    int   i = __float_as_int(t);
    float f = x - (t - 12582912.0f);      // f in [-0.5, 0.5]
    float p = 1.33335581e-3f;
    p = fmaf(p, f, 9.61812911e-3f);
    p = fmaf(p, f, 5.55041087e-2f);
    p = fmaf(p, f, 2.40226507e-1f);
    p = fmaf(p, f, 6.93147181e-1f);
    p = fmaf(p, f, 1.0f);
    float s = __int_as_float((i - 1262485504 + 127) << 23); // 2^round(x)
    return s * p;
}

// ---------------------------------------------------------------------------
// Kernel 1: mask dtype sniffing + valid flags + exclusive prefix scan (1 block)
// ---------------------------------------------------------------------------
__global__ void scan_kernel(const uint8_t* __restrict__ maskraw) {
    __shared__ int s_nz;
    __shared__ int s_sum[1024];
    int tid = threadIdx.x;
    if (tid == 0) s_nz = 0;
    __syncthreads();

    int local = 0;
    for (int i = tid; i < MASKN; i += 1024)
        if (maskraw[i]) local |= 1 << (i & 3);
    if (local) atomicOr(&s_nz, local);
    __syncthreads();

    int nz = s_nz;
    int mode;                       // 0=uint8, 1=int32, 2=float32
    if ((nz & 0xE) == 0)       mode = 1;   // only lowest byte of each 4 nonzero
    else if ((nz & 0x3) == 0)  mode = 2;   // nonzero only in high bytes (1.0f)
    else                       mode = 0;

    int myvalid[8];
    int cnt = 0;
#pragma unroll
    for (int j = 0; j < 8; j++) {
        int t  = tid * 8 + j;
        int b  = t >> 10, r = t & 1023;
        int mi = b * Nn + r + 1;
        int v;
        if (mode == 1)      v = ((const int*)maskraw)[mi] != 0;
        else if (mode == 2) v = ((const float*)maskraw)[mi] != 0.0f;
        else                v = maskraw[mi] != 0;
        myvalid[j] = v;
        cnt += v;
    }
    s_sum[tid] = cnt;
    __syncthreads();
    // Hillis-Steele inclusive scan over 1024 per-thread counts
    for (int off = 1; off < 1024; off <<= 1) {
        int v = s_sum[tid];
        int add = (tid >= off) ? s_sum[tid - off] : 0;
        __syncthreads();
        s_sum[tid] = v + add;
        __syncthreads();
    }
    int excl = s_sum[tid] - cnt;
#pragma unroll
    for (int j = 0; j < 8; j++) {
        int t = tid * 8 + j;
        g_pos[t] = myvalid[j] ? excl : -1;
        excl += myvalid[j];
    }
    if (tid == 1023) g_count = s_sum[1023];
}

// ---------------------------------------------------------------------------
// Kernel 2: normalize + scale + compact gather. One warp per original row.
// q rows scaled by log2(e)/temperature so GEMM yields base-2 exponents.
// ---------------------------------------------------------------------------
__global__ void prep_kernel(const float* __restrict__ qemb,
                            const float* __restrict__ kemb) {
    int gw   = (blockIdx.x * blockDim.x + threadIdx.x) >> 5;
    int lane = threadIdx.x & 31;
    if (gw >= Tt) return;
    int pos = g_pos[gw];
    if (pos < 0) return;
    int b = gw >> 10, r = gw & 1023;
    const float2* qp = (const float2*)(qemb + (size_t)(b * Nn + r) * Dd);
    const float2* kp = (const float2*)(kemb + (size_t)(b * Nn + r + 1) * Dd);
    float2 qv = qp[lane];
    float2 kv = kp[lane];
    float qs = fmaf(qv.x, qv.x, qv.y * qv.y);
    float ks = fmaf(kv.x, kv.x, kv.y * kv.y);
#pragma unroll
    for (int o = 16; o; o >>= 1) {
        qs += __shfl_xor_sync(0xffffffffu, qs, o);
        ks += __shfl_xor_sync(0xffffffffu, ks, o);
    }
    float qn = SCALE_Q / fmaxf(sqrtf(qs), 1e-12f);
    float kn = 1.0f    / fmaxf(sqrtf(ks), 1e-12f);
    ((float2*)(g_qn + (size_t)pos * Dd))[lane] = make_float2(qv.x * qn, qv.y * qn);
    ((float2*)(g_kn + (size_t)pos * Dd))[lane] = make_float2(kv.x * kn, kv.y * kn);
}

// ---------------------------------------------------------------------------
// Kernel 3: 64x128-tiled GEMM + streaming exp2 row-sum.
// grid = (ROWTILES, SPLITS); split s handles column tiles s, s+SPLITS, ...
// ---------------------------------------------------------------------------
__global__ __launch_bounds__(256) void gemm_kernel() {
    __shared__ float qs[Dd][BM];   // [k][m]  16 KB
    __shared__ float ks[Dd][BN];   // [k][n]  32 KB

    int count = g_count;
    int row0  = blockIdx.x * BM;
    if (row0 >= count) return;
    int split = blockIdx.y;
    int tid   = threadIdx.x;
    int tx    = tid & 15;
    int ty    = tid >> 4;

    // Load Q tile (transposed). 256 threads x 16 floats.
    {
        int m  = tid & 63;
        int k4 = tid >> 6;     // 0..3
        const float4* src = (const float4*)(g_qn + (size_t)(row0 + m) * Dd);
#pragma unroll
        for (int it = 0; it < 4; it++) {
            float4 v = src[k4 + it * 4];
            int kk = (k4 + it * 4) * 4;
            qs[kk + 0][m] = v.x; qs[kk + 1][m] = v.y;
            qs[kk + 2][m] = v.z; qs[kk + 3][m] = v.w;
        }
    }

    float acc[4] = {0.f, 0.f, 0.f, 0.f};   // running S per micro-row
    int ntiles = (count + BN - 1) / BN;

    for (int ct = split; ct < ntiles; ct += SPLITS) {
        int col0 = ct * BN;
        __syncthreads();
        // Load K tile (transposed). 256 threads x 32 floats.
        {
            int n  = tid & 127;
            int k4 = tid >> 7;   // 0..1
            const float4* src = (const float4*)(g_kn + (size_t)(col0 + n) * Dd);
#pragma unroll
            for (int it = 0; it < 8; it++) {
                float4 v = src[k4 + it * 2];
                int kk = (k4 + it * 2) * 4;
                ks[kk + 0][n] = v.x; ks[kk + 1][n] = v.y;
                ks[kk + 2][n] = v.z; ks[kk + 3][n] = v.w;
            }
        }
        __syncthreads();

        float dot[4][8];
#pragma unroll
        for (int i = 0; i < 4; i++)
#pragma unroll
            for (int j = 0; j < 8; j++) dot[i][j] = C0x;  // fold -20*log2e into acc

#pragma unroll 4
        for (int kk = 0; kk < Dd; kk++) {
            float4 av  = *(const float4*)&qs[kk][ty * 4];
            float4 bv0 = *(const float4*)&ks[kk][tx * 8];
            float4 bv1 = *(const float4*)&ks[kk][tx * 8 + 4];
            float a[4] = {av.x, av.y, av.z, av.w};
            float b[8] = {bv0.x, bv0.y, bv0.z, bv0.w, bv1.x, bv1.y, bv1.z, bv1.w};
#pragma unroll
            for (int i = 0; i < 4; i++)
#pragma unroll
                for (int j = 0; j < 8; j++)
                    dot[i][j] = fmaf(a[i], b[j], dot[i][j]);
        }

        // Epilogue: exp2 + masked accumulate (pad columns beyond count -> 0)
        float em[8];
#pragma unroll
        for (int j = 0; j < 8; j++)
            em[j] = (col0 + tx * 8 + j < count) ? 1.0f : 0.0f;
#pragma unroll
        for (int i = 0; i < 4; i++)
#pragma unroll
            for (int j = 0; j < 8; j++)
                acc[i] = fmaf(exp2_poly(dot[i][j]), em[j], acc[i]);
    }

    // Reduce the 16 tx lanes of each row (lanes 0-15 / 16-31 within a warp)
#pragma unroll
    for (int i = 0; i < 4; i++) {
        float v = acc[i];
#pragma unroll
        for (int o = 8; o; o >>= 1) v += __shfl_xor_sync(0xffffffffu, v, o);
        if ((threadIdx.x & 15) == 0)
            g_S[split][row0 + ty * 4 + i] = v;
    }
}

// ---------------------------------------------------------------------------
// Kernel 4: diag dot + per-row contribution + two-stage deterministic reduce
// ---------------------------------------------------------------------------
__global__ void reduce_kernel() {
    int count = g_count;
    __shared__ float sblk[8];
    int lane = threadIdx.x & 31;
    int warp = threadIdx.x >> 5;
    int gw   = blockIdx.x * 8 + warp;   // 0..2047
    float wsum = 0.f;
    for (int p = gw; p < count; p += 2048) {
        const float2* qp = (const float2*)(g_qn + (size_t)p * Dd);
        const float2* kp = (const float2*)(g_kn + (size_t)p * Dd);
        float2 q = qp[lane], k = kp[lane];
        float d = fmaf(q.x, k.x, q.y * k.y);
#pragma unroll
        for (int o = 16; o; o >>= 1) d += __shfl_xor_sync(0xffffffffu, d, o);
        if (lane == 0) {
            float S = 0.f;
#pragma unroll
            for (int s = 0; s < SPLITS; s++) S += g_S[s][p];
            wsum += d + C0x - log2f(S);
        }
    }
    if (lane == 0) sblk[warp] = wsum;
    __syncthreads();
    if (threadIdx.x == 0) {
        float b = 0.f;
#pragma unroll
        for (int w = 0; w < 8; w++) b += sblk[w];
        g_bpart[blockIdx.x] = b;
    }
}

__global__ void final_kernel(float* __restrict__ out) {
    if (threadIdx.x == 0) {
        float s = 0.f;
        for (int i = 0; i < 256; i++) s += g_bpart[i];
        out[0] = -LN2f * s / (float)g_count;
    }
}

// ---------------------------------------------------------------------------
extern "C" void kernel_launch(void* const* d_in, const int* in_sizes, int n_in,
                              void* d_out, int out_size) {
    const float*   q = (const float*)d_in[0];
    const float*   k = (const float*)d_in[1];
    const uint8_t* m = (const uint8_t*)d_in[2];
    (void)in_sizes; (void)n_in; (void)out_size;

    scan_kernel<<<1, 1024>>>(m);
    prep_kernel<<<Tt / 8, 256>>>(q, k);
    dim3 grid(ROWTILES, SPLITS);
    gemm_kernel<<<grid, 256>>>();
    reduce_kernel<<<256, 256>>>();
    final_kernel<<<1, 32>>>((float*)d_out);
}

// round 4
// speedup vs baseline: 4.0669x; 4.0669x over previous
#include <cuda_runtime.h>
#include <cuda_bf16.h>
#include <stdint.h>
#include <math.h>

// Problem constants (B=8, N=1025, D=64)
#define Nn     1025
#define Dd     64
#define Tt     8192      // B*(N-1)
#define MASKN  8200      // B*N

#define BM     128
#define BN     128
#define SPLITS 9

#define SCALE_Q 28.85390081777927f   // log2(e)/0.05
#define C0x    (-28.85390081777927f) // -20*log2(e)
#define LN2f    0.6931471805599453f

// Device scratch (zero-initialized at module load; rows >= count stay 0)
__device__ int   g_pos[Tt];
__device__ int   g_count;
__device__ __align__(16) __nv_bfloat16 g_qh[Tt * Dd];
__device__ __align__(16) __nv_bfloat16 g_kh[Tt * Dd];
__device__ float g_diag[Tt];
__device__ float g_S[SPLITS][Tt];
__device__ float g_bpart[32];

// ---------------------------------------------------------------------------
// PTX helpers
// ---------------------------------------------------------------------------
__device__ __forceinline__ float ex2(float x) {
    float r;
    asm("ex2.approx.f32 %0, %1;" : "=f"(r) : "f"(x));
    return r;
}
__device__ __forceinline__ float lg2(float x) {
    float r;
    asm("lg2.approx.f32 %0, %1;" : "=f"(r) : "f"(x));
    return r;
}
__device__ __forceinline__ void ldsm4(uint32_t r[4], uint32_t addr) {
    asm volatile("ldmatrix.sync.aligned.m8n8.x4.shared.b16 {%0,%1,%2,%3}, [%4];"
        : "=r"(r[0]), "=r"(r[1]), "=r"(r[2]), "=r"(r[3]) : "r"(addr));
}
__device__ __forceinline__ void mma16816(float d[4], const uint32_t a[4],
                                         uint32_t b0, uint32_t b1) {
    asm volatile(
        "mma.sync.aligned.m16n8k16.row.col.f32.bf16.bf16.f32 "
        "{%0,%1,%2,%3},{%4,%5,%6,%7},{%8,%9},{%0,%1,%2,%3};"
        : "+f"(d[0]), "+f"(d[1]), "+f"(d[2]), "+f"(d[3])
        : "r"(a[0]), "r"(a[1]), "r"(a[2]), "r"(a[3]), "r"(b0), "r"(b1));
}

// ---------------------------------------------------------------------------
// Kernel 1: mask dtype sniff + valid flags + warp-level prefix scan (1 block)
// ---------------------------------------------------------------------------
__global__ void scan_kernel(const uint8_t* __restrict__ maskraw) {
    __shared__ int s_nz;
    __shared__ int s_warp[32];
    int tid = threadIdx.x, lane = tid & 31, warp = tid >> 5;
    if (tid == 0) s_nz = 0;
    __syncthreads();

    int local = 0;
    for (int i = tid; i < MASKN; i += 1024)
        if (maskraw[i]) local |= 1 << (i & 3);
#pragma unroll
    for (int o = 16; o; o >>= 1) local |= __shfl_xor_sync(0xffffffffu, local, o);
    if (lane == 0 && local) atomicOr(&s_nz, local);
    __syncthreads();

    int nz = s_nz;
    int mode;                       // 0=uint8, 1=int32, 2=float32
    if ((nz & 0xE) == 0)       mode = 1;
    else if ((nz & 0x3) == 0)  mode = 2;
    else                       mode = 0;

    int myvalid[8];
    int cnt = 0;
#pragma unroll
    for (int j = 0; j < 8; j++) {
        int t  = tid * 8 + j;
        int b  = t >> 10, r = t & 1023;
        int mi = b * Nn + r + 1;
        int v;
        if (mode == 1)      v = ((const int*)maskraw)[mi] != 0;
        else if (mode == 2) v = ((const float*)maskraw)[mi] != 0.0f;
        else                v = maskraw[mi] != 0;
        myvalid[j] = v;
        cnt += v;
    }
    // warp inclusive scan
    int inc = cnt;
#pragma unroll
    for (int o = 1; o < 32; o <<= 1) {
        int v = __shfl_up_sync(0xffffffffu, inc, o);
        if (lane >= o) inc += v;
    }
    if (lane == 31) s_warp[warp] = inc;
    __syncthreads();
    if (warp == 0) {
        int v = s_warp[lane];
#pragma unroll
        for (int o = 1; o < 32; o <<= 1) {
            int u = __shfl_up_sync(0xffffffffu, v, o);
            if (lane >= o) v += u;
        }
        s_warp[lane] = v;
    }
    __syncthreads();
    int excl = inc - cnt + (warp ? s_warp[warp - 1] : 0);
#pragma unroll
    for (int j = 0; j < 8; j++) {
        int t = tid * 8 + j;
        g_pos[t] = myvalid[j] ? excl : -1;
        excl += myvalid[j];
    }
    if (tid == 1023) g_count = excl;
}

// ---------------------------------------------------------------------------
// Kernel 2: normalize + scale + bf16 compact gather + diag dot.
// One warp per original row. q scaled by log2(e)/T so GEMM yields base-2 logits.
// ---------------------------------------------------------------------------
__global__ void prep_kernel(const float* __restrict__ qemb,
                            const float* __restrict__ kemb) {
    int gw   = (blockIdx.x * blockDim.x + threadIdx.x) >> 5;
    int lane = threadIdx.x & 31;
    if (gw >= Tt) return;
    int pos = g_pos[gw];
    if (pos < 0) return;
    int b = gw >> 10, r = gw & 1023;
    float2 qv = ((const float2*)(qemb + (size_t)(b * Nn + r) * Dd))[lane];
    float2 kv = ((const float2*)(kemb + (size_t)(b * Nn + r + 1) * Dd))[lane];
    float qs = fmaf(qv.x, qv.x, qv.y * qv.y);
    float ks = fmaf(kv.x, kv.x, kv.y * kv.y);
#pragma unroll
    for (int o = 16; o; o >>= 1) {
        qs += __shfl_xor_sync(0xffffffffu, qs, o);
        ks += __shfl_xor_sync(0xffffffffu, ks, o);
    }
    float qn = SCALE_Q / fmaxf(sqrtf(qs), 1e-12f);
    float kn = 1.0f    / fmaxf(sqrtf(ks), 1e-12f);
    __nv_bfloat162 qb = __floats2bfloat162_rn(qv.x * qn, qv.y * qn);
    __nv_bfloat162 kb = __floats2bfloat162_rn(kv.x * kn, kv.y * kn);
    ((__nv_bfloat162*)(g_qh + (size_t)pos * Dd))[lane] = qb;
    ((__nv_bfloat162*)(g_kh + (size_t)pos * Dd))[lane] = kb;
    // diagonal logit (log2 units) from the same bf16-rounded values
    float d = fmaf(__bfloat162float(qb.x), __bfloat162float(kb.x),
                   __bfloat162float(qb.y) * __bfloat162float(kb.y));
#pragma unroll
    for (int o = 16; o; o >>= 1) d += __shfl_xor_sync(0xffffffffu, d, o);
    if (lane == 0) g_diag[pos] = d;
}

// ---------------------------------------------------------------------------
// Kernel 3: 128x128 bf16 tensor-core GEMM + fused exp2 row-sum.
// grid = (Tt/BM, SPLITS); 8 warps = 4(m) x 2(n); warp tile 32x64.
// ---------------------------------------------------------------------------
__global__ __launch_bounds__(256, 2) void gemm_kernel() {
    __shared__ __align__(16) uint4 As[BM * 8];   // 16 KB, swizzled
    __shared__ __align__(16) uint4 Bs[BN * 8];   // 16 KB, swizzled
    __shared__ float ssum[2][BM];

    int count = g_count;
    int row0  = blockIdx.x * BM;
    if (row0 >= count) return;
    int split = blockIdx.y;
    int tid   = threadIdx.x;
    int lane  = tid & 31;
    int wid   = tid >> 5;
    int wm    = wid & 3;      // 0..3 : rows wm*32
    int wn    = wid >> 2;     // 0..1 : cols wn*64

    uint32_t asb = (uint32_t)__cvta_generic_to_shared(As);
    uint32_t bsb = (uint32_t)__cvta_generic_to_shared(Bs);

    // Load A tile (swizzled): chunk = 16B = 8 bf16
    {
        const uint4* src = (const uint4*)(g_qh + (size_t)row0 * Dd);
#pragma unroll
        for (int i = 0; i < 4; i++) {
            int c = tid + i * 256;
            int r = c >> 3, k16 = c & 7;
            As[r * 8 + (k16 ^ (r & 7))] = src[c];
        }
    }
    __syncthreads();

    // Hoist all A fragments (rows wm*32..+32, full K=64)
    uint32_t afrag[2][4][4];
#pragma unroll
    for (int mi = 0; mi < 2; mi++)
#pragma unroll
        for (int ks = 0; ks < 4; ks++) {
            int m = lane >> 3;
            int r = wm * 32 + mi * 16 + ((m & 1) << 3) + (lane & 7);
            int c = 2 * ks + (m >> 1);
            ldsm4(afrag[mi][ks], asb + (uint32_t)(r * 8 + (c ^ (r & 7))) * 16);
        }

    float rsum[4] = {0.f, 0.f, 0.f, 0.f};
    int ntiles = (count + BN - 1) >> 7;

    for (int ct = split; ct < ntiles; ct += SPLITS) {
        int col0 = ct << 7;
        __syncthreads();
        {
            const uint4* src = (const uint4*)(g_kh + (size_t)col0 * Dd);
#pragma unroll
            for (int i = 0; i < 4; i++) {
                int c = tid + i * 256;
                int r = c >> 3, k16 = c & 7;
                Bs[r * 8 + (k16 ^ (r & 7))] = src[c];
            }
        }
        __syncthreads();
        bool full = (col0 + BN) <= count;

#pragma unroll
        for (int nh = 0; nh < 2; nh++) {
            float acc[2][4][4];
#pragma unroll
            for (int mi = 0; mi < 2; mi++)
#pragma unroll
                for (int ni = 0; ni < 4; ni++)
#pragma unroll
                    for (int j = 0; j < 4; j++) acc[mi][ni][j] = C0x;

#pragma unroll
            for (int ks = 0; ks < 4; ks++) {
                uint32_t bfr[2][4];
#pragma unroll
                for (int p = 0; p < 2; p++) {
                    int ni0 = nh * 4 + p * 2;
                    int m = lane >> 3;
                    int r = wn * 64 + ni0 * 8 + ((m >> 1) << 3) + (lane & 7);
                    int c = 2 * ks + (m & 1);
                    ldsm4(bfr[p], bsb + (uint32_t)(r * 8 + (c ^ (r & 7))) * 16);
                }
#pragma unroll
                for (int mi = 0; mi < 2; mi++) {
                    mma16816(acc[mi][0], afrag[mi][ks], bfr[0][0], bfr[0][1]);
                    mma16816(acc[mi][1], afrag[mi][ks], bfr[0][2], bfr[0][3]);
                    mma16816(acc[mi][2], afrag[mi][ks], bfr[1][0], bfr[1][1]);
                    mma16816(acc[mi][3], afrag[mi][ks], bfr[1][2], bfr[1][3]);
                }
            }

            if (full) {
#pragma unroll
                for (int mi = 0; mi < 2; mi++)
#pragma unroll
                    for (int ni = 0; ni < 4; ni++) {
                        rsum[mi * 2 + 0] += ex2(acc[mi][ni][0]) + ex2(acc[mi][ni][1]);
                        rsum[mi * 2 + 1] += ex2(acc[mi][ni][2]) + ex2(acc[mi][ni][3]);
                    }
            } else {
                int cb = col0 + wn * 64 + nh * 32 + (lane & 3) * 2;
#pragma unroll
                for (int mi = 0; mi < 2; mi++)
#pragma unroll
                    for (int ni = 0; ni < 4; ni++) {
                        int c0 = cb + ni * 8;
                        float e0 = (c0     < count) ? ex2(acc[mi][ni][0]) : 0.f;
                        float e1 = (c0 + 1 < count) ? ex2(acc[mi][ni][1]) : 0.f;
                        float e2 = (c0     < count) ? ex2(acc[mi][ni][2]) : 0.f;
                        float e3 = (c0 + 1 < count) ? ex2(acc[mi][ni][3]) : 0.f;
                        rsum[mi * 2 + 0] += e0 + e1;
                        rsum[mi * 2 + 1] += e2 + e3;
                    }
            }
        }
    }

    // lanes sharing a row: l%4 (column quads)
#pragma unroll
    for (int i = 0; i < 4; i++) {
        rsum[i] += __shfl_xor_sync(0xffffffffu, rsum[i], 1);
        rsum[i] += __shfl_xor_sync(0xffffffffu, rsum[i], 2);
    }
    if ((lane & 3) == 0) {
#pragma unroll
        for (int i = 0; i < 4; i++) {
            int row = wm * 32 + (i >> 1) * 16 + (i & 1) * 8 + (lane >> 2);
            ssum[wn][row] = rsum[i];
        }
    }
    __syncthreads();
    if (tid < BM)
        g_S[split][row0 + tid] = ssum[0][tid] + ssum[1][tid];
}

// ---------------------------------------------------------------------------
// Kernel 4: per-row loss + deterministic block reduce
// logp_diag (log2) = diag - (log2(S) - C0)  [S carries the C0 shift]
// ---------------------------------------------------------------------------
__global__ void reduce_kernel() {
    __shared__ float sblk[8];
    int r = blockIdx.x * 256 + threadIdx.x;
    int count = g_count;
    float v = 0.f;
    if (r < count) {
        float S = 0.f;
#pragma unroll
        for (int s = 0; s < SPLITS; s++) S += g_S[s][r];
        v = g_diag[r] + C0x - lg2(S);
    }
#pragma unroll
    for (int o = 16; o; o >>= 1) v += __shfl_xor_sync(0xffffffffu, v, o);
    int lane = threadIdx.x & 31, warp = threadIdx.x >> 5;
    if (lane == 0) sblk[warp] = v;
    __syncthreads();
    if (threadIdx.x == 0) {
        float b = 0.f;
#pragma unroll
        for (int w = 0; w < 8; w++) b += sblk[w];
        g_bpart[blockIdx.x] = b;
    }
}

__global__ void final_kernel(float* __restrict__ out) {
    if (threadIdx.x == 0) {
        float s = 0.f;
#pragma unroll
        for (int i = 0; i < 32; i++) s += g_bpart[i];
        out[0] = -LN2f * s / (float)g_count;
    }
}

// ---------------------------------------------------------------------------
extern "C" void kernel_launch(void* const* d_in, const int* in_sizes, int n_in,
                              void* d_out, int out_size) {
    const float*   q = (const float*)d_in[0];
    const float*   k = (const float*)d_in[1];
    const uint8_t* m = (const uint8_t*)d_in[2];
    (void)in_sizes; (void)n_in; (void)out_size;

    scan_kernel<<<1, 1024>>>(m);
    prep_kernel<<<Tt / 8, 256>>>(q, k);
    dim3 grid(Tt / BM, SPLITS);
    gemm_kernel<<<grid, 256>>>();
    reduce_kernel<<<32, 256>>>();
    final_kernel<<<1, 32>>>((float*)d_out);
}

// round 5
// speedup vs baseline: 4.3790x; 1.0767x over previous
#include <cuda_runtime.h>
#include <cuda_bf16.h>
#include <stdint.h>
#include <math.h>

// Problem constants (B=8, N=1025, D=64)
#define Nn     1025
#define Dd     64
#define Tt     8192      // B*(N-1)
#define MASKN  8200      // B*N

#define BM     128
#define BN     128
#define SPLITS 8

#define SCALE_Q 28.85390081777927f   // log2(e)/0.05
#define C0x    (-28.85390081777927f) // -20*log2(e)
#define LN2f    0.6931471805599453f

// Device scratch (zero-initialized at module load; rows >= count stay 0)
__device__ int   g_count;
__device__ int   g_done;
__device__ __align__(16) __nv_bfloat16 g_qh[Tt * Dd];
__device__ __align__(16) __nv_bfloat16 g_kh[Tt * Dd];
__device__ float g_diag[Tt];
__device__ __align__(32) float g_S2[Tt * SPLITS];   // [row][split]
__device__ volatile float g_bpart[32];

// ---------------------------------------------------------------------------
// PTX helpers
// ---------------------------------------------------------------------------
__device__ __forceinline__ float ex2(float x) {
    float r;
    asm("ex2.approx.f32 %0, %1;" : "=f"(r) : "f"(x));
    return r;
}
__device__ __forceinline__ float lg2(float x) {
    float r;
    asm("lg2.approx.f32 %0, %1;" : "=f"(r) : "f"(x));
    return r;
}
__device__ __forceinline__ void ldsm4(uint32_t r[4], uint32_t addr) {
    asm volatile("ldmatrix.sync.aligned.m8n8.x4.shared.b16 {%0,%1,%2,%3}, [%4];"
        : "=r"(r[0]), "=r"(r[1]), "=r"(r[2]), "=r"(r[3]) : "r"(addr));
}
__device__ __forceinline__ void mma16816(float d[4], const uint32_t a[4],
                                         uint32_t b0, uint32_t b1) {
    asm volatile(
        "mma.sync.aligned.m16n8k16.row.col.f32.bf16.bf16.f32 "
        "{%0,%1,%2,%3},{%4,%5,%6,%7},{%8,%9},{%0,%1,%2,%3};"
        : "+f"(d[0]), "+f"(d[1]), "+f"(d[2]), "+f"(d[3])
        : "r"(a[0]), "r"(a[1]), "r"(a[2]), "r"(a[3]), "r"(b0), "r"(b1));
}

// ---------------------------------------------------------------------------
// Kernel 1: fused mask-scan + normalize + bf16 compact gather + diag dot.
// 256 blocks x 1024 threads. Each block redundantly scans the full mask
// (L2-hot, ~8KB) and derives compact positions for its own 32 rows
// (one warp per row).
// ---------------------------------------------------------------------------
__global__ __launch_bounds__(1024) void prep_kernel(const float* __restrict__ qemb,
                                                    const float* __restrict__ kemb,
                                                    const uint8_t* __restrict__ maskraw) {
    __shared__ int s_nz;
    __shared__ int s_warp[32];
    __shared__ int s_pos[32];
    int tid = threadIdx.x, lane = tid & 31, warp = tid >> 5;
    if (tid == 0) s_nz = 0;
    __syncthreads();

    // dtype sniff: which byte positions within 4-byte groups are nonzero
    int local = 0;
    for (int i = tid; i < MASKN; i += 1024)
        if (maskraw[i]) local |= 1 << (i & 3);
#pragma unroll
    for (int o = 16; o; o >>= 1) local |= __shfl_xor_sync(0xffffffffu, local, o);
    if (lane == 0 && local) atomicOr(&s_nz, local);
    __syncthreads();

    int nz = s_nz;
    int mode;                       // 0=uint8, 1=int32, 2=float32
    if ((nz & 0xE) == 0)       mode = 1;
    else if ((nz & 0x3) == 0)  mode = 2;
    else                       mode = 0;

    int myvalid[8];
    int cnt = 0;
#pragma unroll
    for (int j = 0; j < 8; j++) {
        int t  = tid * 8 + j;
        int b  = t >> 10, r = t & 1023;
        int mi = b * Nn + r + 1;
        int v;
        if (mode == 1)      v = ((const int*)maskraw)[mi] != 0;
        else if (mode == 2) v = ((const float*)maskraw)[mi] != 0.0f;
        else                v = maskraw[mi] != 0;
        myvalid[j] = v;
        cnt += v;
    }
    // warp inclusive scan
    int inc = cnt;
#pragma unroll
    for (int o = 1; o < 32; o <<= 1) {
        int v = __shfl_up_sync(0xffffffffu, inc, o);
        if (lane >= o) inc += v;
    }
    if (lane == 31) s_warp[warp] = inc;
    __syncthreads();
    if (warp == 0) {
        int v = s_warp[lane];
#pragma unroll
        for (int o = 1; o < 32; o <<= 1) {
            int u = __shfl_up_sync(0xffffffffu, v, o);
            if (lane >= o) v += u;
        }
        s_warp[lane] = v;
    }
    __syncthreads();
    int excl = inc - cnt + (warp ? s_warp[warp - 1] : 0);

    int br0 = blockIdx.x * 32;
    int e = excl;
#pragma unroll
    for (int j = 0; j < 8; j++) {
        int t = tid * 8 + j;
        if (t >= br0 && t < br0 + 32)
            s_pos[t - br0] = myvalid[j] ? e : -1;
        e += myvalid[j];
    }
    if (blockIdx.x == 0 && tid == 1023) {
        g_count = e;          // total valid
        g_done  = 0;          // reset last-block counter for this replay
    }
    __syncthreads();

    int row = br0 + warp;     // one warp per original row
    int pos = s_pos[warp];
    if (pos < 0) return;
    int b = row >> 10, r = row & 1023;
    float2 qv = ((const float2*)(qemb + (size_t)(b * Nn + r) * Dd))[lane];
    float2 kv = ((const float2*)(kemb + (size_t)(b * Nn + r + 1) * Dd))[lane];
    float qs = fmaf(qv.x, qv.x, qv.y * qv.y);
    float ks = fmaf(kv.x, kv.x, kv.y * kv.y);
#pragma unroll
    for (int o = 16; o; o >>= 1) {
        qs += __shfl_xor_sync(0xffffffffu, qs, o);
        ks += __shfl_xor_sync(0xffffffffu, ks, o);
    }
    float qn = SCALE_Q / fmaxf(sqrtf(qs), 1e-12f);
    float kn = 1.0f    / fmaxf(sqrtf(ks), 1e-12f);
    __nv_bfloat162 qb = __floats2bfloat162_rn(qv.x * qn, qv.y * qn);
    __nv_bfloat162 kb = __floats2bfloat162_rn(kv.x * kn, kv.y * kn);
    ((__nv_bfloat162*)(g_qh + (size_t)pos * Dd))[lane] = qb;
    ((__nv_bfloat162*)(g_kh + (size_t)pos * Dd))[lane] = kb;
    float d = fmaf(__bfloat162float(qb.x), __bfloat162float(kb.x),
                   __bfloat162float(qb.y) * __bfloat162float(kb.y));
#pragma unroll
    for (int o = 16; o; o >>= 1) d += __shfl_xor_sync(0xffffffffu, d, o);
    if (lane == 0) g_diag[pos] = d;
}

// ---------------------------------------------------------------------------
// Kernel 2: 128x128 bf16 tensor-core GEMM + fused exp2 row-sum.
// grid = (Tt/BM, SPLITS); 8 warps = 4(m) x 2(n); warp tile 32x64.
// ---------------------------------------------------------------------------
__global__ __launch_bounds__(256, 2) void gemm_kernel() {
    __shared__ __align__(16) uint4 As[BM * 8];   // 16 KB, swizzled
    __shared__ __align__(16) uint4 Bs[BN * 8];   // 16 KB, swizzled
    __shared__ float ssum[2][BM];

    int count = g_count;
    int row0  = blockIdx.x * BM;
    if (row0 >= count) return;
    int split = blockIdx.y;
    int tid   = threadIdx.x;
    int lane  = tid & 31;
    int wid   = tid >> 5;
    int wm    = wid & 3;      // 0..3 : rows wm*32
    int wn    = wid >> 2;     // 0..1 : cols wn*64

    uint32_t asb = (uint32_t)__cvta_generic_to_shared(As);
    uint32_t bsb = (uint32_t)__cvta_generic_to_shared(Bs);

    // Load A tile (swizzled): chunk = 16B = 8 bf16
    {
        const uint4* src = (const uint4*)(g_qh + (size_t)row0 * Dd);
#pragma unroll
        for (int i = 0; i < 4; i++) {
            int c = tid + i * 256;
            int r = c >> 3, k16 = c & 7;
            As[r * 8 + (k16 ^ (r & 7))] = src[c];
        }
    }
    __syncthreads();

    // Hoist all A fragments (rows wm*32..+32, full K=64)
    uint32_t afrag[2][4][4];
#pragma unroll
    for (int mi = 0; mi < 2; mi++)
#pragma unroll
        for (int ks = 0; ks < 4; ks++) {
            int m = lane >> 3;
            int r = wm * 32 + mi * 16 + ((m & 1) << 3) + (lane & 7);
            int c = 2 * ks + (m >> 1);
            ldsm4(afrag[mi][ks], asb + (uint32_t)(r * 8 + (c ^ (r & 7))) * 16);
        }

    float rsum[4] = {0.f, 0.f, 0.f, 0.f};
    int ntiles = (count + BN - 1) >> 7;

    for (int ct = split; ct < ntiles; ct += SPLITS) {
        int col0 = ct << 7;
        __syncthreads();
        {
            const uint4* src = (const uint4*)(g_kh + (size_t)col0 * Dd);
#pragma unroll
            for (int i = 0; i < 4; i++) {
                int c = tid + i * 256;
                int r = c >> 3, k16 = c & 7;
                Bs[r * 8 + (k16 ^ (r & 7))] = src[c];
            }
        }
        __syncthreads();
        bool full = (col0 + BN) <= count;

#pragma unroll
        for (int nh = 0; nh < 2; nh++) {
            float acc[2][4][4];
#pragma unroll
            for (int mi = 0; mi < 2; mi++)
#pragma unroll
                for (int ni = 0; ni < 4; ni++)
#pragma unroll
                    for (int j = 0; j < 4; j++) acc[mi][ni][j] = C0x;

#pragma unroll
            for (int ks = 0; ks < 4; ks++) {
                uint32_t bfr[2][4];
#pragma unroll
                for (int p = 0; p < 2; p++) {
                    int ni0 = nh * 4 + p * 2;
                    int m = lane >> 3;
                    int r = wn * 64 + ni0 * 8 + ((m >> 1) << 3) + (lane & 7);
                    int c = 2 * ks + (m & 1);
                    ldsm4(bfr[p], bsb + (uint32_t)(r * 8 + (c ^ (r & 7))) * 16);
                }
#pragma unroll
                for (int mi = 0; mi < 2; mi++) {
                    mma16816(acc[mi][0], afrag[mi][ks], bfr[0][0], bfr[0][1]);
                    mma16816(acc[mi][1], afrag[mi][ks], bfr[0][2], bfr[0][3]);
                    mma16816(acc[mi][2], afrag[mi][ks], bfr[1][0], bfr[1][1]);
                    mma16816(acc[mi][3], afrag[mi][ks], bfr[1][2], bfr[1][3]);
                }
            }

            if (full) {
#pragma unroll
                for (int mi = 0; mi < 2; mi++)
#pragma unroll
                    for (int ni = 0; ni < 4; ni++) {
                        rsum[mi * 2 + 0] += ex2(acc[mi][ni][0]) + ex2(acc[mi][ni][1]);
                        rsum[mi * 2 + 1] += ex2(acc[mi][ni][2]) + ex2(acc[mi][ni][3]);
                    }
            } else {
                int cb = col0 + wn * 64 + nh * 32 + (lane & 3) * 2;
#pragma unroll
                for (int mi = 0; mi < 2; mi++)
#pragma unroll
                    for (int ni = 0; ni < 4; ni++) {
                        int c0 = cb + ni * 8;
                        float e0 = (c0     < count) ? ex2(acc[mi][ni][0]) : 0.f;
                        float e1 = (c0 + 1 < count) ? ex2(acc[mi][ni][1]) : 0.f;
                        float e2 = (c0     < count) ? ex2(acc[mi][ni][2]) : 0.f;
                        float e3 = (c0 + 1 < count) ? ex2(acc[mi][ni][3]) : 0.f;
                        rsum[mi * 2 + 0] += e0 + e1;
                        rsum[mi * 2 + 1] += e2 + e3;
                    }
            }
        }
    }

    // lanes sharing a row: l%4 (column quads)
#pragma unroll
    for (int i = 0; i < 4; i++) {
        rsum[i] += __shfl_xor_sync(0xffffffffu, rsum[i], 1);
        rsum[i] += __shfl_xor_sync(0xffffffffu, rsum[i], 2);
    }
    if ((lane & 3) == 0) {
#pragma unroll
        for (int i = 0; i < 4; i++) {
            int row = wm * 32 + (i >> 1) * 16 + (i & 1) * 8 + (lane >> 2);
            ssum[wn][row] = rsum[i];
        }
    }
    __syncthreads();
    if (tid < BM)
        g_S2[(size_t)(row0 + tid) * SPLITS + split] = ssum[0][tid] + ssum[1][tid];
}

// ---------------------------------------------------------------------------
// Kernel 3: per-row loss + deterministic reduce + fused final (last block).
// logp_diag (log2) = diag + C0 - log2(S)   [S carries the C0 shift]
// ---------------------------------------------------------------------------
__global__ void reduce_kernel(float* __restrict__ out) {
    __shared__ float sblk[8];
    int r = blockIdx.x * 256 + threadIdx.x;
    int count = g_count;
    float v = 0.f;
    if (r < count) {
        float4 a = *(const float4*)&g_S2[(size_t)r * SPLITS];
        float4 b = *(const float4*)&g_S2[(size_t)r * SPLITS + 4];
        float S = ((a.x + a.y) + (a.z + a.w)) + ((b.x + b.y) + (b.z + b.w));
        v = g_diag[r] + C0x - lg2(S);
    }
#pragma unroll
    for (int o = 16; o; o >>= 1) v += __shfl_xor_sync(0xffffffffu, v, o);
    int lane = threadIdx.x & 31, warp = threadIdx.x >> 5;
    if (lane == 0) sblk[warp] = v;
    __syncthreads();
    if (threadIdx.x == 0) {
        float bsum = 0.f;
#pragma unroll
        for (int w = 0; w < 8; w++) bsum += sblk[w];
        g_bpart[blockIdx.x] = bsum;
        __threadfence();
        int t = atomicAdd(&g_done, 1);
        if (t == 31) {
            __threadfence();
            float s = 0.f;
#pragma unroll
            for (int i = 0; i < 32; i++) s += g_bpart[i];
            out[0] = -LN2f * s / (float)count;
        }
    }
}

// ---------------------------------------------------------------------------
extern "C" void kernel_launch(void* const* d_in, const int* in_sizes, int n_in,
                              void* d_out, int out_size) {
    const float*   q = (const float*)d_in[0];
    const float*   k = (const float*)d_in[1];
    const uint8_t* m = (const uint8_t*)d_in[2];
    (void)in_sizes; (void)n_in; (void)out_size;

    prep_kernel<<<Tt / 32, 1024>>>(q, k, m);
    dim3 grid(Tt / BM, SPLITS);
    gemm_kernel<<<grid, 256>>>();
    reduce_kernel<<<32, 256>>>((float*)d_out);
}